// round 1
// baseline (speedup 1.0000x reference)
#include <cuda_runtime.h>
#include <cuda_bf16.h>
#include <float.h>

// Problem shape (fixed by the benchmark's setup_inputs)
#define B_  64
#define T_  256
#define V_  6625
#define S_  25
#define SX_ 51          // 2*S+1
#define NEG_ (-1e30f)

// Scratch (no allocations allowed -> __device__ globals)
__device__ float g_emit[B_ * T_ * SX_];   // emit[b][t][s] = logp[b,t,ext[s]]
__device__ float g_loss[B_];              // per-batch loss / length

// ---------------------------------------------------------------------------
// Kernel 1: per-(b,t) logsumexp over V (single pass, register-blocked) and
// gather of the 51 extended-label emissions.
// grid = (T, B), block = 256
// ---------------------------------------------------------------------------
#define K1_THREADS 256
#define K1_PER_THREAD ((V_ + K1_THREADS - 1) / K1_THREADS)   // 26

__device__ __forceinline__ void lse_merge(float& m, float& s, float mo, float so) {
    float nm = fmaxf(m, mo);
    s = s * __expf(m - nm) + so * __expf(mo - nm);
    m = nm;
}

__global__ __launch_bounds__(K1_THREADS)
void lse_emit_kernel(const float* __restrict__ pred,
                     const int*   __restrict__ target) {
    const int t = blockIdx.x;
    const int b = blockIdx.y;
    const float* __restrict__ row = pred + (size_t)(b * T_ + t) * V_;
    const int tid = threadIdx.x;

    // Load my strided slice of the row into registers.
    float vals[K1_PER_THREAD];
    float m = -FLT_MAX;
#pragma unroll
    for (int i = 0; i < K1_PER_THREAD; ++i) {
        int idx = tid + i * K1_THREADS;
        vals[i] = (idx < V_) ? row[idx] : -FLT_MAX;
        m = fmaxf(m, vals[i]);
    }
    float s = 0.f;
#pragma unroll
    for (int i = 0; i < K1_PER_THREAD; ++i) {
        s += __expf(vals[i] - m);   // __expf(-huge) == 0 for the padded lanes
    }

    // Warp reduce (m, s)
#pragma unroll
    for (int off = 16; off > 0; off >>= 1) {
        float mo = __shfl_down_sync(0xffffffffu, m, off);
        float so = __shfl_down_sync(0xffffffffu, s, off);
        lse_merge(m, s, mo, so);
    }

    __shared__ float sh_m[8], sh_s[8];
    __shared__ float sh_lse;
    const int wid = tid >> 5, lane = tid & 31;
    if (lane == 0) { sh_m[wid] = m; sh_s[wid] = s; }
    __syncthreads();
    if (wid == 0) {
        m = (lane < 8) ? sh_m[lane] : -FLT_MAX;
        s = (lane < 8) ? sh_s[lane] : 0.f;
#pragma unroll
        for (int off = 4; off > 0; off >>= 1) {
            float mo = __shfl_down_sync(0xffffffffu, m, off);
            float so = __shfl_down_sync(0xffffffffu, s, off);
            lse_merge(m, s, mo, so);
        }
        if (lane == 0) sh_lse = m + __logf(s);
    }
    __syncthreads();
    const float lse = sh_lse;

    // Gather the 51 extended-label emissions (blank, l1, blank, l2, ..., blank)
    if (tid < SX_) {
        int lab = (tid & 1) ? target[b * S_ + (tid >> 1)] : 0;
        g_emit[(size_t)(b * T_ + t) * SX_ + tid] = row[lab] - lse;
    }
}

// ---------------------------------------------------------------------------
// Kernel 2: CTC forward recursion, one block per batch, 64 threads.
// Double-buffered alpha in shared memory; one __syncthreads per time step.
// Next step's emit is prefetched to hide L2 latency behind the step chain.
// ---------------------------------------------------------------------------
__global__ __launch_bounds__(64)
void ctc_forward_kernel(const int* __restrict__ target,
                        const int* __restrict__ length) {
    const int b = blockIdx.x;
    const int s = threadIdx.x;              // state index; threads >= SX_ idle
    const bool active = (s < SX_);

    __shared__ float abuf[2][SX_];

    const float* __restrict__ eb = g_emit + (size_t)b * T_ * SX_;

    // Per-state constants: label, skip flag
    bool skip = false;
    if (active) {
        int lab   = (s & 1) ? target[b * S_ + ((s - 1) >> 1)] : 0;
        int prev2 = (s >= 2) ? (((s - 2) & 1) ? target[b * S_ + ((s - 3) >> 1)] : 0) : 0;
        skip = (lab != 0) && (lab != prev2);
    }

    // alpha at t=0
    if (active) abuf[0][s] = (s <= 1) ? eb[s] : NEG_;
    float e_next = active ? eb[SX_ + s] : 0.f;   // emit for t=1
    __syncthreads();

    int cur = 0;
    for (int t = 1; t < T_; ++t) {
        float out = NEG_;
        float e_cur = e_next;
        if (active && t + 1 < T_) e_next = eb[(size_t)(t + 1) * SX_ + s];
        if (active) {
            float a1 = abuf[cur][s];
            float a2 = (s >= 1) ? abuf[cur][s - 1] : NEG_;
            float a3 = (skip && s >= 2) ? abuf[cur][s - 2] : NEG_;
            float m  = fmaxf(a1, fmaxf(a2, a3));
            float lse = m + __logf(__expf(a1 - m) + __expf(a2 - m) + __expf(a3 - m));
            out = lse + e_cur;
        }
        if (active) abuf[cur ^ 1][s] = out;
        __syncthreads();
        cur ^= 1;
    }

    if (s == 0) {
        int L = length[b];
        float a1 = abuf[cur][2 * L - 1];
        float a2 = abuf[cur][2 * L];
        float m  = fmaxf(a1, a2);
        float ll = m + logf(expf(a1 - m) + expf(a2 - m));
        float loss = -ll;
        if (!isfinite(loss)) loss = 0.f;
        g_loss[b] = loss / (float)L;
    }
}

// ---------------------------------------------------------------------------
// Kernel 3: mean over batch -> scalar
// ---------------------------------------------------------------------------
__global__ void reduce_kernel(float* __restrict__ out) {
    const int tid = threadIdx.x;   // 32 threads
    float v = g_loss[tid] + g_loss[tid + 32];
#pragma unroll
    for (int off = 16; off > 0; off >>= 1)
        v += __shfl_down_sync(0xffffffffu, v, off);
    if (tid == 0) out[0] = v / (float)B_;
}

// ---------------------------------------------------------------------------
extern "C" void kernel_launch(void* const* d_in, const int* in_sizes, int n_in,
                              void* d_out, int out_size) {
    const float* pred   = (const float*)d_in[0];
    const int*   target = (const int*)d_in[1];
    const int*   length = (const int*)d_in[2];
    float* out = (float*)d_out;

    dim3 g1(T_, B_);
    lse_emit_kernel<<<g1, K1_THREADS>>>(pred, target);
    ctc_forward_kernel<<<B_, 64>>>(target, length);
    reduce_kernel<<<1, 32>>>(out);
}

// round 2
// speedup vs baseline: 1.6841x; 1.6841x over previous
#include <cuda_runtime.h>
#include <cuda_bf16.h>
#include <float.h>

#define B_  64
#define T_  256
#define V_  6625
#define S_  25
#define SX_ 51          // 2*S+1
#define SXP_ 52         // padded stride (aligned float2 per lane-pair)
#define NEG_ (-1e30f)

// Scratch (no allocations allowed -> __device__ globals)
__device__ float2 g_emit2[B_ * T_ * (SXP_ / 2)];  // emit[b][t][s], stride 52 floats
__device__ float  g_loss[B_];

// ---------------------------------------------------------------------------
// Kernel 1: per-(b,t) logsumexp over V (single pass, float4 register-blocked)
// and gather of the 51 extended-label emissions.  grid=(T,B), block=256
// ---------------------------------------------------------------------------
#define K1_THREADS 256

__device__ __forceinline__ void lse_merge(float& m, float& s, float mo, float so) {
    float nm = fmaxf(m, mo);
    s = s * __expf(m - nm) + so * __expf(mo - nm);
    m = nm;
}

__global__ __launch_bounds__(K1_THREADS)
void lse_emit_kernel(const float* __restrict__ pred,
                     const int*   __restrict__ target) {
    const int t = blockIdx.x;
    const int b = blockIdx.y;
    const int tid = threadIdx.x;
    const size_t base = (size_t)(b * T_ + t) * V_;
    const float* __restrict__ row = pred + base;

    // Alignment phase: rows are only 4B-aligned (V=6625). Peel to 16B boundary.
    const int head = (int)((4 - (base & 3)) & 3);
    const int nv4  = (V_ - head) >> 2;                 // 1655 or 1656
    const int tailc = V_ - head - (nv4 << 2);
    const float4* __restrict__ rv = reinterpret_cast<const float4*>(row + head);

    float4 v[7];
#pragma unroll
    for (int i = 0; i < 7; ++i) {
        int q = tid + (i << 8);
        if (q < nv4) v[i] = rv[q];
        else         v[i] = make_float4(-FLT_MAX, -FLT_MAX, -FLT_MAX, -FLT_MAX);
    }
    float ex0 = (tid < head)  ? row[tid] : -FLT_MAX;
    float ex1 = (tid < tailc) ? row[head + (nv4 << 2) + tid] : -FLT_MAX;

    float m = fmaxf(ex0, ex1);
#pragma unroll
    for (int i = 0; i < 7; ++i)
        m = fmaxf(m, fmaxf(fmaxf(v[i].x, v[i].y), fmaxf(v[i].z, v[i].w)));

    float s = __expf(ex0 - m) + __expf(ex1 - m);
#pragma unroll
    for (int i = 0; i < 7; ++i)
        s += __expf(v[i].x - m) + __expf(v[i].y - m)
           + __expf(v[i].z - m) + __expf(v[i].w - m);

    // Warp reduce (m, s)
#pragma unroll
    for (int off = 16; off > 0; off >>= 1) {
        float mo = __shfl_down_sync(0xffffffffu, m, off);
        float so = __shfl_down_sync(0xffffffffu, s, off);
        lse_merge(m, s, mo, so);
    }

    __shared__ float sh_m[8], sh_s[8];
    __shared__ float sh_lse;
    const int wid = tid >> 5, lane = tid & 31;
    if (lane == 0) { sh_m[wid] = m; sh_s[wid] = s; }
    __syncthreads();
    if (wid == 0) {
        m = (lane < 8) ? sh_m[lane] : -FLT_MAX;
        s = (lane < 8) ? sh_s[lane] : 0.f;
#pragma unroll
        for (int off = 4; off > 0; off >>= 1) {
            float mo = __shfl_down_sync(0xffffffffu, m, off);
            float so = __shfl_down_sync(0xffffffffu, s, off);
            lse_merge(m, s, mo, so);
        }
        if (lane == 0) sh_lse = m + __logf(s);
    }
    __syncthreads();
    const float lse = sh_lse;

    // Gather the 51 extended-label emissions (blank, l1, blank, ..., blank)
    if (tid < SX_) {
        int lab = (tid & 1) ? target[b * S_ + (tid >> 1)] : 0;
        reinterpret_cast<float*>(g_emit2)[(size_t)(b * T_ + t) * SXP_ + tid] = row[lab] - lse;
    }
}

// ---------------------------------------------------------------------------
// Kernel 2: CTC forward recursion. ONE WARP per batch, no barriers, no smem.
// Lane i holds states (2i, 2i+1). Recursion needs only p_hi = shfl_up(hi,1):
//   new_lo(2i)   = lse(lo, p_hi)                + e.x   (blank: no skip path)
//   new_hi(2i+1) = lse(hi, lo, skip ? p_hi : -) + e.y
// Emit prefetched 4 steps ahead in a statically-indexed register ring.
// ---------------------------------------------------------------------------
__device__ __forceinline__ float lse2f(float a, float b) {
    float m = fmaxf(a, b);
    return m + __logf(__expf(a - m) + __expf(b - m));
}
__device__ __forceinline__ float lse3f(float a, float b, float c) {
    float m = fmaxf(a, fmaxf(b, c));
    return m + __logf(__expf(a - m) + __expf(b - m) + __expf(c - m));
}

__global__ __launch_bounds__(32)
void ctc_forward_kernel(const int* __restrict__ target,
                        const int* __restrict__ length) {
    const int b = blockIdx.x;
    const int lane = threadIdx.x;
    const bool act = (lane < 26);
    const float2 nf2 = make_float2(NEG_, NEG_);

    // skip flag for odd state 2*lane+1 (label = target[lane], prev2 = target[lane-1])
    bool skip_hi = false;
    if (act && lane > 0 && lane < 25) {
        int la = target[b * S_ + lane];
        int lp = target[b * S_ + lane - 1];
        skip_hi = (la != lp);
    }
    // lane 0: a3 path is NEG anyway (p_hi forced NEG); lane 25 hi-state is invalid/discarded.

    const float2* __restrict__ ep =
        g_emit2 + (size_t)(b * T_) * (SXP_ / 2) + lane;

    float2 er0 = act ? ep[0 * (SXP_/2)] : nf2;
    float2 er1 = act ? ep[1 * (SXP_/2)] : nf2;
    float2 er2 = act ? ep[2 * (SXP_/2)] : nf2;
    float2 er3 = act ? ep[3 * (SXP_/2)] : nf2;

    // alpha at t=0
    float lo = (lane == 0) ? er0.x : NEG_;
    float hi = (lane == 0) ? er0.y : NEG_;

#define CTC_STEP(ESLOT, TCUR)                                             \
    {                                                                      \
        float2 e = ESLOT;                                                  \
        int tp = (TCUR) + 4;                                               \
        if (act && tp < T_) ESLOT = ep[(size_t)tp * (SXP_/2)];             \
        float p_hi = __shfl_up_sync(0xffffffffu, hi, 1);                   \
        if (lane == 0) p_hi = NEG_;                                        \
        float nlo = lse2f(lo, p_hi) + e.x;                                 \
        float a3  = skip_hi ? p_hi : NEG_;                                 \
        float nhi = lse3f(hi, lo, a3) + e.y;                               \
        lo = nlo; hi = nhi;                                                \
    }

    int t = 1;
#pragma unroll 1
    for (int g = 0; g < 63; ++g) {       // t = 1..252, slots 1,2,3,0
        CTC_STEP(er1, t);
        CTC_STEP(er2, t + 1);
        CTC_STEP(er3, t + 2);
        CTC_STEP(er0, t + 3);
        t += 4;
    }
    CTC_STEP(er1, 253);
    CTC_STEP(er2, 254);
    CTC_STEP(er3, 255);
#undef CTC_STEP

    // Final: ll = logsumexp(alpha[2L-1], alpha[2L])
    int L = length[b];
    float ah = __shfl_sync(0xffffffffu, hi, L - 1);  // state 2L-1
    float al = __shfl_sync(0xffffffffu, lo, L);      // state 2L
    if (lane == 0) {
        float m  = fmaxf(ah, al);
        float ll = m + logf(expf(ah - m) + expf(al - m));
        float loss = -ll;
        if (!isfinite(loss)) loss = 0.f;
        g_loss[b] = loss / (float)L;
    }
}

// ---------------------------------------------------------------------------
// Kernel 3: mean over batch -> scalar
// ---------------------------------------------------------------------------
__global__ void reduce_kernel(float* __restrict__ out) {
    const int tid = threadIdx.x;   // 32 threads
    float v = g_loss[tid] + g_loss[tid + 32];
#pragma unroll
    for (int off = 16; off > 0; off >>= 1)
        v += __shfl_down_sync(0xffffffffu, v, off);
    if (tid == 0) out[0] = v / (float)B_;
}

// ---------------------------------------------------------------------------
extern "C" void kernel_launch(void* const* d_in, const int* in_sizes, int n_in,
                              void* d_out, int out_size) {
    const float* pred   = (const float*)d_in[0];
    const int*   target = (const int*)d_in[1];
    const int*   length = (const int*)d_in[2];
    float* out = (float*)d_out;

    dim3 g1(T_, B_);
    lse_emit_kernel<<<g1, K1_THREADS>>>(pred, target);
    ctc_forward_kernel<<<B_, 32>>>(target, length);
    reduce_kernel<<<1, 32>>>(out);
}